// round 2
// baseline (speedup 1.0000x reference)
#include <cuda_runtime.h>

#define NN 100000
#define FD 32

// Scratch (static device globals — no allocation in kernel_launch)
__device__ float g_scaled[NN * FD];  // (h @ W) * dinv[src], per node
__device__ float g_agg[NN * FD];     // accumulator, init to scaled (self-loop)
__device__ float g_h[NN * FD];       // layer activation
__device__ float g_dinv[NN];
__device__ int   g_deg[NN];

__global__ void k_init_deg() {
    int i = blockIdx.x * blockDim.x + threadIdx.x;
    if (i < NN) g_deg[i] = 1;  // self-loop contributes 1
}

__global__ void k_count(const int* __restrict__ dst, int E) {
    int e = blockIdx.x * blockDim.x + threadIdx.x;
    if (e < E) atomicAdd(&g_deg[dst[e]], 1);
}

__global__ void k_dinv() {
    int i = blockIdx.x * blockDim.x + threadIdx.x;
    if (i < NN) g_dinv[i] = rsqrtf((float)g_deg[i]);
}

// One warp per node: lane f computes (row @ W)[f], scales by dinv[node],
// writes g_scaled and initializes g_agg with it (folds self-loop term).
// use_h: layer >= 1 reads g_h instead of x.
__global__ __launch_bounds__(256) void k_transform(const float* __restrict__ x,
                                                   const float* __restrict__ W,
                                                   int use_h) {
    __shared__ float Ws[FD * FD];
    int tid = threadIdx.x;
    #pragma unroll
    for (int i = tid; i < FD * FD; i += 256) Ws[i] = W[i];
    __syncthreads();

    int g = blockIdx.x * 256 + tid;
    int node = g >> 5;
    int lane = g & 31;
    if (node >= NN) return;  // whole warps exit together (node uniform per warp)

    const float* in = use_h ? g_h : x;
    float xv = in[node * FD + lane];
    float acc = 0.0f;
    #pragma unroll
    for (int k = 0; k < FD; k++)
        acc = fmaf(__shfl_sync(0xffffffffu, xv, k), Ws[k * FD + lane], acc);

    float s = acc * g_dinv[node];
    int idx = node * FD + lane;
    g_scaled[idx] = s;
    g_agg[idx]    = s;
}

// 8 lanes per edge; each lane moves one float4 (16B) with a vectorized red.
__global__ __launch_bounds__(256) void k_scatter(const int* __restrict__ src,
                                                 const int* __restrict__ dst,
                                                 int E) {
    long long t = (long long)blockIdx.x * 256 + threadIdx.x;
    int e = (int)(t >> 3);
    if (e >= E) return;
    int q = ((int)t & 7) << 2;   // feature offset 0,4,...,28

    int s = src[e];
    int d = dst[e];

    const float4 v = *reinterpret_cast<const float4*>(&g_scaled[s * FD + q]);
    float* a = &g_agg[d * FD + q];
    asm volatile("red.global.add.v4.f32 [%0], {%1, %2, %3, %4};"
                 :: "l"(a), "f"(v.x), "f"(v.y), "f"(v.z), "f"(v.w)
                 : "memory");
}

// h = relu(dinv[node] * agg + b)
__global__ void k_finish(const float* __restrict__ b) {
    int idx = blockIdx.x * blockDim.x + threadIdx.x;
    if (idx >= NN * FD) return;
    int node = idx >> 5;
    int f = idx & 31;
    float v = g_dinv[node] * g_agg[idx] + b[f];
    g_h[idx] = fmaxf(v, 0.0f);
}

// Fused: h1 = relu(dinv*agg + b1);  out = h1 @ Wf + bf
__global__ __launch_bounds__(256) void k_final(const float* __restrict__ b1,
                                               const float* __restrict__ Wf,
                                               const float* __restrict__ bf,
                                               float* __restrict__ out) {
    __shared__ float Ws[FD * FD];
    __shared__ float bfs[FD];
    int tid = threadIdx.x;
    #pragma unroll
    for (int i = tid; i < FD * FD; i += 256) Ws[i] = Wf[i];
    if (tid < FD) bfs[tid] = bf[tid];
    __syncthreads();

    int g = blockIdx.x * 256 + tid;
    int node = g >> 5;
    int lane = g & 31;
    if (node >= NN) return;

    float hv = fmaxf(g_dinv[node] * g_agg[node * FD + lane] + b1[lane], 0.0f);
    float acc = bfs[lane];
    #pragma unroll
    for (int k = 0; k < FD; k++)
        acc = fmaf(__shfl_sync(0xffffffffu, hv, k), Ws[k * FD + lane], acc);

    out[node * FD + lane] = acc;
}

extern "C" void kernel_launch(void* const* d_in, const int* in_sizes, int n_in,
                              void* d_out, int out_size) {
    const float* x   = (const float*)d_in[0];
    const int*   ei  = (const int*)d_in[1];   // JAX x64 disabled -> int32
    const float* W0  = (const float*)d_in[2];
    const float* b0  = (const float*)d_in[3];
    const float* W1  = (const float*)d_in[4];
    const float* b1  = (const float*)d_in[5];
    const float* Wf  = (const float*)d_in[6];
    const float* bf  = (const float*)d_in[7];
    float* out = (float*)d_out;

    int E = in_sizes[1] / 2;          // edge_index is [2, E]
    const int* src = ei;
    const int* dst = ei + E;

    int nb_n  = (NN + 255) / 256;
    int nb_e  = (E + 255) / 256;
    int nb_nf = (NN * FD + 255) / 256;            // 1 warp per node => NN*32 threads
    long long sthreads = (long long)E * 8;
    int nb_s  = (int)((sthreads + 255) / 256);

    // degree + normalization
    k_init_deg<<<nb_n, 256>>>();
    k_count<<<nb_e, 256>>>(dst, E);
    k_dinv<<<nb_n, 256>>>();

    // layer 0
    k_transform<<<nb_nf, 256>>>(x, W0, 0);
    k_scatter<<<nb_s, 256>>>(src, dst, E);
    k_finish<<<nb_nf, 256>>>(b0);

    // layer 1 + fused final linear
    k_transform<<<nb_nf, 256>>>(x, W1, 1);
    k_scatter<<<nb_s, 256>>>(src, dst, E);
    k_final<<<nb_nf, 256>>>(b1, Wf, bf, out);
}

// round 3
// speedup vs baseline: 1.2587x; 1.2587x over previous
#include <cuda_runtime.h>

#define NN 100000
#define FD 32
#define NPW 32   // nodes processed per warp (amortizes W-column register load)

// Scratch (static device globals — no allocation in kernel_launch)
__device__ float g_scaled[NN * FD];  // (h @ W) * dinv[src], per node
__device__ float g_agg[NN * FD];     // accumulator, init to scaled (self-loop)
__device__ float g_dinv[NN];
__device__ int   g_deg[NN];

__global__ void k_init_deg() {
    int i = blockIdx.x * blockDim.x + threadIdx.x;
    if (i < NN) g_deg[i] = 1;  // self-loop contributes 1
}

// Vectorized degree count: int4 index loads, 4 scattered REDs per thread.
__global__ void k_count(const int* __restrict__ dst, int E) {
    int t = blockIdx.x * blockDim.x + threadIdx.x;
    int e = t * 4;
    if (e + 3 < E) {
        int4 d = *reinterpret_cast<const int4*>(dst + e);
        atomicAdd(&g_deg[d.x], 1);
        atomicAdd(&g_deg[d.y], 1);
        atomicAdd(&g_deg[d.z], 1);
        atomicAdd(&g_deg[d.w], 1);
    } else {
        for (int i = e; i < E; i++) atomicAdd(&g_deg[dst[i]], 1);
    }
}

__global__ void k_dinv() {
    int i = blockIdx.x * blockDim.x + threadIdx.x;
    if (i < NN) g_dinv[i] = rsqrtf((float)g_deg[i]);
}

// Layer-0 transform: lane l holds W[:,l] in registers; x row read via
// 8 uniform-address float4 loads (broadcast, L1-resident). One warp does
// NPW nodes. Writes g_scaled and seeds g_agg (self-loop term folded).
__global__ __launch_bounds__(256) void k_xform0(const float* __restrict__ x,
                                                const float* __restrict__ W) {
    int lane = threadIdx.x & 31;
    int w = blockIdx.x * 8 + (threadIdx.x >> 5);
    int base = w * NPW;
    if (base >= NN) return;

    float Wc[FD];
    #pragma unroll
    for (int k = 0; k < FD; k++) Wc[k] = W[k * FD + lane];  // coalesced

    int end = min(base + NPW, NN);
    for (int node = base; node < end; node++) {
        const float4* xr = reinterpret_cast<const float4*>(x + (size_t)node * FD);
        float acc = 0.0f;
        #pragma unroll
        for (int j = 0; j < FD / 4; j++) {
            float4 v = __ldg(xr + j);                 // warp-uniform broadcast
            acc = fmaf(v.x, Wc[4 * j + 0], acc);
            acc = fmaf(v.y, Wc[4 * j + 1], acc);
            acc = fmaf(v.z, Wc[4 * j + 2], acc);
            acc = fmaf(v.w, Wc[4 * j + 3], acc);
        }
        float s = acc * g_dinv[node];
        g_scaled[node * FD + lane] = s;
        g_agg[node * FD + lane]    = s;
    }
}

// Layer-1 transform fused with epilogue of layer 0:
//   h = relu(dinv*agg + b0)  (computed coalesced, staged in shared)
//   scaled = (h @ W1) * dinv
__global__ __launch_bounds__(256) void k_xform1(const float* __restrict__ W,
                                                const float* __restrict__ b) {
    __shared__ float s_h[8][FD];
    int lane = threadIdx.x & 31;
    int wb = threadIdx.x >> 5;
    int w = blockIdx.x * 8 + wb;
    int base = w * NPW;
    if (base >= NN) return;

    float Wc[FD];
    #pragma unroll
    for (int k = 0; k < FD; k++) Wc[k] = W[k * FD + lane];
    float bl = b[lane];

    int end = min(base + NPW, NN);
    for (int node = base; node < end; node++) {
        float dv = g_dinv[node];
        float h = fmaxf(dv * g_agg[node * FD + lane] + bl, 0.0f);
        s_h[wb][lane] = h;
        __syncwarp();
        const float4* hr = reinterpret_cast<const float4*>(s_h[wb]);
        float acc = 0.0f;
        #pragma unroll
        for (int j = 0; j < FD / 4; j++) {
            float4 v = hr[j];                          // broadcast LDS.128
            acc = fmaf(v.x, Wc[4 * j + 0], acc);
            acc = fmaf(v.y, Wc[4 * j + 1], acc);
            acc = fmaf(v.z, Wc[4 * j + 2], acc);
            acc = fmaf(v.w, Wc[4 * j + 3], acc);
        }
        __syncwarp();                                  // protect s_h reuse
        float s = acc * dv;
        g_scaled[node * FD + lane] = s;
        g_agg[node * FD + lane]    = s;
    }
}

// Final: h1 = relu(dinv*agg + b1); out = h1 @ Wf + bf   (same structure)
__global__ __launch_bounds__(256) void k_final(const float* __restrict__ b1,
                                               const float* __restrict__ Wf,
                                               const float* __restrict__ bf,
                                               float* __restrict__ out) {
    __shared__ float s_h[8][FD];
    int lane = threadIdx.x & 31;
    int wb = threadIdx.x >> 5;
    int w = blockIdx.x * 8 + wb;
    int base = w * NPW;
    if (base >= NN) return;

    float Wc[FD];
    #pragma unroll
    for (int k = 0; k < FD; k++) Wc[k] = Wf[k * FD + lane];
    float b1l = b1[lane];
    float bfl = bf[lane];

    int end = min(base + NPW, NN);
    for (int node = base; node < end; node++) {
        float dv = g_dinv[node];
        float h = fmaxf(dv * g_agg[node * FD + lane] + b1l, 0.0f);
        s_h[wb][lane] = h;
        __syncwarp();
        const float4* hr = reinterpret_cast<const float4*>(s_h[wb]);
        float acc = 0.0f;
        #pragma unroll
        for (int j = 0; j < FD / 4; j++) {
            float4 v = hr[j];
            acc = fmaf(v.x, Wc[4 * j + 0], acc);
            acc = fmaf(v.y, Wc[4 * j + 1], acc);
            acc = fmaf(v.z, Wc[4 * j + 2], acc);
            acc = fmaf(v.w, Wc[4 * j + 3], acc);
        }
        __syncwarp();
        out[node * FD + lane] = acc + bfl;
    }
}

// 8 lanes per edge; each lane moves one float4 (16B) with a vectorized red.
__global__ __launch_bounds__(256) void k_scatter(const int* __restrict__ src,
                                                 const int* __restrict__ dst,
                                                 int E) {
    long long t = (long long)blockIdx.x * 256 + threadIdx.x;
    int e = (int)(t >> 3);
    if (e >= E) return;
    int q = ((int)t & 7) << 2;   // feature offset 0,4,...,28

    int s = src[e];
    int d = dst[e];

    const float4 v = *reinterpret_cast<const float4*>(&g_scaled[s * FD + q]);
    float* a = &g_agg[d * FD + q];
    asm volatile("red.global.add.v4.f32 [%0], {%1, %2, %3, %4};"
                 :: "l"(a), "f"(v.x), "f"(v.y), "f"(v.z), "f"(v.w)
                 : "memory");
}

extern "C" void kernel_launch(void* const* d_in, const int* in_sizes, int n_in,
                              void* d_out, int out_size) {
    const float* x   = (const float*)d_in[0];
    const int*   ei  = (const int*)d_in[1];   // JAX x64 disabled -> int32
    const float* W0  = (const float*)d_in[2];
    const float* b0  = (const float*)d_in[3];
    const float* W1  = (const float*)d_in[4];
    const float* b1  = (const float*)d_in[5];
    const float* Wf  = (const float*)d_in[6];
    const float* bf  = (const float*)d_in[7];
    float* out = (float*)d_out;

    int E = in_sizes[1] / 2;          // edge_index is [2, E]
    const int* src = ei;
    const int* dst = ei + E;

    int nb_n = (NN + 255) / 256;
    int nb_c = ((E + 3) / 4 + 255) / 256;
    int warps = (NN + NPW - 1) / NPW;           // 3125
    int nb_x  = (warps + 7) / 8;                // 8 warps/block
    long long sthreads = (long long)E * 8;
    int nb_s  = (int)((sthreads + 255) / 256);

    // degree + normalization
    k_init_deg<<<nb_n, 256>>>();
    k_count<<<nb_c, 256>>>(dst, E);
    k_dinv<<<nb_n, 256>>>();

    // layer 0
    k_xform0<<<nb_x, 256>>>(x, W0);
    k_scatter<<<nb_s, 256>>>(src, dst, E);

    // layer 1 (epilogue of layer 0 fused in)
    k_xform1<<<nb_x, 256>>>(W1, b0);
    k_scatter<<<nb_s, 256>>>(src, dst, E);

    // final linear (epilogue of layer 1 fused in)
    k_final<<<nb_x, 256>>>(b1, Wf, bf, out);
}

// round 4
// speedup vs baseline: 1.3422x; 1.0663x over previous
#include <cuda_runtime.h>

#define NN 100000
#define FD 32
#define NPW 8    // nodes per warp: small => high warp count, latency hiding

// Scratch (static device globals — no allocation in kernel_launch)
__device__ float g_scaled[NN * FD];  // (h @ W) * dinv[src], per node
__device__ float g_agg[NN * FD];     // accumulator, init to scaled (self-loop)
__device__ float g_dinv[NN];
__device__ int   g_deg[NN];

__global__ void k_init_deg() {
    int i = blockIdx.x * blockDim.x + threadIdx.x;
    if (i < NN) g_deg[i] = 1;  // self-loop contributes 1
}

// Vectorized degree count: int4 index loads, 4 scattered REDs per thread.
__global__ void k_count(const int* __restrict__ dst, int E) {
    int t = blockIdx.x * blockDim.x + threadIdx.x;
    int e = t * 4;
    if (e + 3 < E) {
        int4 d = *reinterpret_cast<const int4*>(dst + e);
        atomicAdd(&g_deg[d.x], 1);
        atomicAdd(&g_deg[d.y], 1);
        atomicAdd(&g_deg[d.z], 1);
        atomicAdd(&g_deg[d.w], 1);
    } else {
        for (int i = e; i < E; i++) atomicAdd(&g_deg[dst[i]], 1);
    }
}

__global__ void k_dinv() {
    int i = blockIdx.x * blockDim.x + threadIdx.x;
    if (i < NN) g_dinv[i] = rsqrtf((float)g_deg[i]);
}

// Layer-0 transform: lane l holds W[:,l] in registers; x row read via
// 8 uniform-address float4 loads (broadcast). One warp does NPW nodes.
// Writes g_scaled and seeds g_agg (self-loop term folded).
__global__ __launch_bounds__(256) void k_xform0(const float* __restrict__ x,
                                                const float* __restrict__ W) {
    int lane = threadIdx.x & 31;
    int w = blockIdx.x * 8 + (threadIdx.x >> 5);
    int base = w * NPW;
    if (base >= NN) return;

    float Wc[FD];
    #pragma unroll
    for (int k = 0; k < FD; k++) Wc[k] = W[k * FD + lane];  // coalesced

    #pragma unroll
    for (int u = 0; u < NPW; u++) {
        int node = base + u;   // NN % NPW == 0, no tail
        const float4* xr = reinterpret_cast<const float4*>(x + (size_t)node * FD);
        float acc = 0.0f;
        #pragma unroll
        for (int j = 0; j < FD / 4; j++) {
            float4 v = __ldg(xr + j);                 // warp-uniform broadcast
            acc = fmaf(v.x, Wc[4 * j + 0], acc);
            acc = fmaf(v.y, Wc[4 * j + 1], acc);
            acc = fmaf(v.z, Wc[4 * j + 2], acc);
            acc = fmaf(v.w, Wc[4 * j + 3], acc);
        }
        float s = acc * g_dinv[node];
        g_scaled[node * FD + lane] = s;
        g_agg[node * FD + lane]    = s;
    }
}

// Layer-1 transform fused with epilogue of layer 0:
//   h = relu(dinv*agg + b0)  (computed coalesced, staged in shared)
//   scaled = (h @ W1) * dinv
__global__ __launch_bounds__(256) void k_xform1(const float* __restrict__ W,
                                                const float* __restrict__ b) {
    __shared__ float s_h[8][FD];
    int lane = threadIdx.x & 31;
    int wb = threadIdx.x >> 5;
    int w = blockIdx.x * 8 + wb;
    int base = w * NPW;
    if (base >= NN) return;

    float Wc[FD];
    #pragma unroll
    for (int k = 0; k < FD; k++) Wc[k] = W[k * FD + lane];
    float bl = b[lane];

    #pragma unroll
    for (int u = 0; u < NPW; u++) {
        int node = base + u;
        float dv = g_dinv[node];
        float h = fmaxf(dv * g_agg[node * FD + lane] + bl, 0.0f);
        s_h[wb][lane] = h;
        __syncwarp();
        const float4* hr = reinterpret_cast<const float4*>(s_h[wb]);
        float acc = 0.0f;
        #pragma unroll
        for (int j = 0; j < FD / 4; j++) {
            float4 v = hr[j];                          // broadcast LDS.128
            acc = fmaf(v.x, Wc[4 * j + 0], acc);
            acc = fmaf(v.y, Wc[4 * j + 1], acc);
            acc = fmaf(v.z, Wc[4 * j + 2], acc);
            acc = fmaf(v.w, Wc[4 * j + 3], acc);
        }
        __syncwarp();                                  // protect s_h reuse
        float s = acc * dv;
        g_scaled[node * FD + lane] = s;
        g_agg[node * FD + lane]    = s;
    }
}

// Final: h1 = relu(dinv*agg + b1); out = h1 @ Wf + bf   (same structure)
__global__ __launch_bounds__(256) void k_final(const float* __restrict__ b1,
                                               const float* __restrict__ Wf,
                                               const float* __restrict__ bf,
                                               float* __restrict__ out) {
    __shared__ float s_h[8][FD];
    int lane = threadIdx.x & 31;
    int wb = threadIdx.x >> 5;
    int w = blockIdx.x * 8 + wb;
    int base = w * NPW;
    if (base >= NN) return;

    float Wc[FD];
    #pragma unroll
    for (int k = 0; k < FD; k++) Wc[k] = Wf[k * FD + lane];
    float b1l = b1[lane];
    float bfl = bf[lane];

    #pragma unroll
    for (int u = 0; u < NPW; u++) {
        int node = base + u;
        float dv = g_dinv[node];
        float h = fmaxf(dv * g_agg[node * FD + lane] + b1l, 0.0f);
        s_h[wb][lane] = h;
        __syncwarp();
        const float4* hr = reinterpret_cast<const float4*>(s_h[wb]);
        float acc = 0.0f;
        #pragma unroll
        for (int j = 0; j < FD / 4; j++) {
            float4 v = hr[j];
            acc = fmaf(v.x, Wc[4 * j + 0], acc);
            acc = fmaf(v.y, Wc[4 * j + 1], acc);
            acc = fmaf(v.z, Wc[4 * j + 2], acc);
            acc = fmaf(v.w, Wc[4 * j + 3], acc);
        }
        __syncwarp();
        out[node * FD + lane] = acc + bfl;
    }
}

// 8 lanes per edge; each lane moves one float4 (16B) with a vectorized red.
__global__ __launch_bounds__(256) void k_scatter(const int* __restrict__ src,
                                                 const int* __restrict__ dst,
                                                 int E) {
    long long t = (long long)blockIdx.x * 256 + threadIdx.x;
    int e = (int)(t >> 3);
    if (e >= E) return;
    int q = ((int)t & 7) << 2;   // feature offset 0,4,...,28

    int s = src[e];
    int d = dst[e];

    const float4 v = *reinterpret_cast<const float4*>(&g_scaled[s * FD + q]);
    float* a = &g_agg[d * FD + q];
    asm volatile("red.global.add.v4.f32 [%0], {%1, %2, %3, %4};"
                 :: "l"(a), "f"(v.x), "f"(v.y), "f"(v.z), "f"(v.w)
                 : "memory");
}

extern "C" void kernel_launch(void* const* d_in, const int* in_sizes, int n_in,
                              void* d_out, int out_size) {
    const float* x   = (const float*)d_in[0];
    const int*   ei  = (const int*)d_in[1];   // JAX x64 disabled -> int32
    const float* W0  = (const float*)d_in[2];
    const float* b0  = (const float*)d_in[3];
    const float* W1  = (const float*)d_in[4];
    const float* b1  = (const float*)d_in[5];
    const float* Wf  = (const float*)d_in[6];
    const float* bf  = (const float*)d_in[7];
    float* out = (float*)d_out;

    int E = in_sizes[1] / 2;          // edge_index is [2, E]
    const int* src = ei;
    const int* dst = ei + E;

    int nb_n = (NN + 255) / 256;
    int nb_c = ((E + 3) / 4 + 255) / 256;
    int warps = (NN + NPW - 1) / NPW;           // 12500
    int nb_x  = (warps + 7) / 8;                // 8 warps/block -> 1563 blocks
    long long sthreads = (long long)E * 8;
    int nb_s  = (int)((sthreads + 255) / 256);

    // degree + normalization
    k_init_deg<<<nb_n, 256>>>();
    k_count<<<nb_c, 256>>>(dst, E);
    k_dinv<<<nb_n, 256>>>();

    // layer 0
    k_xform0<<<nb_x, 256>>>(x, W0);
    k_scatter<<<nb_s, 256>>>(src, dst, E);

    // layer 1 (epilogue of layer 0 fused in)
    k_xform1<<<nb_x, 256>>>(W1, b0);
    k_scatter<<<nb_s, 256>>>(src, dst, E);

    // final linear (epilogue of layer 1 fused in)
    k_final<<<nb_x, 256>>>(b1, Wf, bf, out);
}